// round 15
// baseline (speedup 1.0000x reference)
#include <cuda_runtime.h>
#include <math.h>

#define DIMV 32
#define KN 16
#define NREL 60
#define MAXB 8192

// scratch (device globals)
__device__ float g_uemb [MAXB * DIMV];
__device__ int   g_e1id [MAXB * KN];
__device__ float g_attn0[MAXB * KN];
__device__ int   g_e2id [MAXB * KN * KN];
__device__ float g_attn1[MAXB * KN * KN];
__device__ float g_t    [MAXB * KN * DIMV];

__device__ __forceinline__ float sigm(float x) { return 1.f / (1.f + __expf(-x)); }

__device__ __forceinline__ float softmax16(float sc) {
    float m = sc;
    #pragma unroll
    for (int o = 8; o > 0; o >>= 1) m = fmaxf(m, __shfl_xor_sync(0xffffffffu, m, o, 16));
    float e = __expf(sc - m);
    float s = e;
    #pragma unroll
    for (int o = 8; o > 0; o >>= 1) s += __shfl_xor_sync(0xffffffffu, s, o, 16);
    return e / s;
}

__device__ __forceinline__ float udr_lookup(float u0, float u1, int rid) {
    float a = __shfl_sync(0xffffffffu, u0, rid & 31);
    float b = __shfl_sync(0xffffffffu, u1, rid & 31);
    return (rid < 32) ? a : b;
}

// ---- KA: 2 warps per element; hop-2 phase split, prefix duplicated. ------
__global__ __launch_bounds__(256, 8) void ka_kernel(
    const int*   __restrict__ users,
    const int*   __restrict__ items,
    const float* __restrict__ emb,
    const float* __restrict__ rel,
    const int*   __restrict__ adjE,
    const int*   __restrict__ adjR,
    const int*   __restrict__ hist,
    int B)
{
    __shared__ float rels[NREL * DIMV];   // swizzled [r*32 + ((d+r)&31)]

    const int tid = threadIdx.x, lane = tid & 31, w = tid >> 5;
    #pragma unroll
    for (int i = tid; i < NREL * DIMV; i += 256) {
        int r = i >> 5, d = i & 31;
        rels[r * DIMV + ((d + r) & 31)] = __ldg(&rel[i]);
    }
    __syncthreads();

    const int b    = blockIdx.x * 4 + (w >> 1);
    const int half = w & 1;
    if (b >= B) return;

    const int uid  = __ldg(&users[b]);
    const int item = __ldg(&items[b]);
    const int kl   = lane & 15;

    const int hid = __ldg(&hist[(size_t)uid  * KN + kl]);
    const int e1  = __ldg(&adjE[(size_t)item * KN + kl]);
    const int r0  = __ldg(&adjR[(size_t)item * KN + kl]);

    // user embedding (duplicated per half; 2nd warp's loads hit L1/L2)
    float hv[8];
    float us = 0.f;
    #pragma unroll
    for (int h = 0; h < 2; ++h) {
        #pragma unroll
        for (int k = 0; k < 8; ++k) {
            int id = __shfl_sync(0xffffffffu, hid, h * 8 + k);
            hv[k] = __ldg(&emb[(size_t)id * DIMV + lane]);
        }
        #pragma unroll
        for (int k = 0; k < 8; ++k) us += hv[k];
    }
    const float uemb = us * (1.f / 16.f);

    // udotr: lane r holds udotr[r] (u0) and udotr[r+32] (u1)
    float u0 = 0.f, u1 = 0.f;
    const int r2 = lane + 32;
    #pragma unroll
    for (int d = 0; d < DIMV; ++d) {
        float ud = __shfl_sync(0xffffffffu, uemb, d);
        u0 += ud * rels[lane * DIMV + ((d + lane) & 31)];
        if (r2 < NREL) u1 += ud * rels[r2 * DIMV + ((d + r2) & 31)];
    }

    if (half == 0) {
        g_uemb[b * DIMV + lane] = uemb;
        float a0 = softmax16(udr_lookup(u0, u1, r0));
        if (lane < KN) {
            g_e1id [b * KN + lane] = e1;
            g_attn0[b * KN + lane] = a0;
        }
    }

    // hop-2 adjacency + hop-1 attention: this half does rows half*8..+7
    #pragma unroll
    for (int p = 0; p < 4; ++p) {
        int row  = half * 8 + 2 * p + (lane >> 4);
        int base = __shfl_sync(0xffffffffu, e1, row);
        int id   = __ldg(&adjE[(size_t)base * KN + kl]);
        int rid  = __ldg(&adjR[(size_t)base * KN + kl]);
        float a  = softmax16(udr_lookup(u0, u1, rid));
        size_t o = (size_t)b * 256 + row * KN + kl;
        g_e2id [o] = id;
        g_attn1[o] = a;
    }
}

// ---- KB: warp per quad. Pipelined gather + quad-batched matvec (R14). ----
__global__ __launch_bounds__(256, 5) void kb_kernel(
    const float* __restrict__ emb,
    const float* __restrict__ W,
    const float* __restrict__ bvec,
    int B)
{
    __shared__ float Ws[DIMV * DIMV];
    __shared__ float bs[DIMV];

    const int tid = threadIdx.x, lane = tid & 31, w = tid >> 5;
    #pragma unroll
    for (int i = tid; i < DIMV * DIMV; i += 256) Ws[i] = __ldg(&W[i]);
    if (tid < DIMV) bs[tid] = __ldg(&bvec[tid]);
    __syncthreads();

    const int q = blockIdx.x * 8 + w;
    const int b = q >> 2, quad = q & 3;
    if (b >= B) return;

    const int2*   idp = (const int2*)  (g_e2id  + (size_t)b * 256 + quad * 64);
    const float2* wtp = (const float2*)(g_attn1 + (size_t)b * 256 + quad * 64);
    const int2   id2 = __ldg(&idp[lane]);
    const float2 wt2 = __ldg(&wtp[lane]);

    const int s4 = (lane < 4) ? __ldg(&g_e1id[b * KN + quad * 4 + lane]) : 0;
    float xacc[4];
    #pragma unroll
    for (int t = 0; t < 4; ++t) {
        int sid = __shfl_sync(0xffffffffu, s4, t);
        xacc[t] = __ldg(&emb[(size_t)sid * DIMV + lane]);
    }

    float va[4], vb[4], na[4], nb[4];
    #pragma unroll
    for (int p = 0; p < 4; ++p) {
        int ia = __shfl_sync(0xffffffffu, id2.x, p);
        int ib = __shfl_sync(0xffffffffu, id2.y, p);
        va[p] = __ldg(&emb[(size_t)ia * DIMV + lane]);
        vb[p] = __ldg(&emb[(size_t)ib * DIMV + lane]);
    }

    #pragma unroll
    for (int t = 0; t < 4; ++t) {
        #pragma unroll
        for (int h = 0; h < 2; ++h) {
            const int nt = (h == 1) ? t + 1 : t;
            const int nh = (h == 1) ? 0 : 1;
            if (nt < 4) {
                #pragma unroll
                for (int p = 0; p < 4; ++p) {
                    int src = nt * 8 + nh * 4 + p;
                    int ia = __shfl_sync(0xffffffffu, id2.x, src);
                    int ib = __shfl_sync(0xffffffffu, id2.y, src);
                    na[p] = __ldg(&emb[(size_t)ia * DIMV + lane]);
                    nb[p] = __ldg(&emb[(size_t)ib * DIMV + lane]);
                }
            }
            #pragma unroll
            for (int p = 0; p < 4; ++p) {
                int src = t * 8 + h * 4 + p;
                xacc[t] += __shfl_sync(0xffffffffu, wt2.x, src) * va[p];
                xacc[t] += __shfl_sync(0xffffffffu, wt2.y, src) * vb[p];
            }
            #pragma unroll
            for (int p = 0; p < 4; ++p) { va[p] = na[p]; vb[p] = nb[p]; }
        }
    }

    // quad-batched matvec: each Ws row read once, feeds all 4 tasks
    float y0 = bs[lane], y1 = y0, y2 = y0, y3 = y0;
    #pragma unroll
    for (int j = 0; j < DIMV; ++j) {
        float wj = Ws[j * DIMV + lane];
        y0 += __shfl_sync(0xffffffffu, xacc[0], j) * wj;
        y1 += __shfl_sync(0xffffffffu, xacc[1], j) * wj;
        y2 += __shfl_sync(0xffffffffu, xacc[2], j) * wj;
        y3 += __shfl_sync(0xffffffffu, xacc[3], j) * wj;
    }

    float* tp = g_t + ((size_t)b * KN + quad * 4) * DIMV + lane;
    tp[0 * DIMV] = sigm(y0);
    tp[1 * DIMV] = sigm(y1);
    tp[2 * DIMV] = sigm(y2);
    tp[3 * DIMV] = sigm(y3);
}

// ---- KC: warp per element; shared W for occupancy. -----------------------
__global__ __launch_bounds__(256, 6) void kc_kernel(
    const int*   __restrict__ items,
    const float* __restrict__ emb,
    const float* __restrict__ W,
    const float* __restrict__ bvec,
    float*       __restrict__ out,
    int B)
{
    __shared__ float Ws[DIMV * DIMV];
    __shared__ float bs[DIMV];

    const int tid = threadIdx.x, lane = tid & 31, w = tid >> 5;
    #pragma unroll
    for (int i = tid; i < DIMV * DIMV; i += 256) Ws[i] = __ldg(&W[i]);
    if (tid < DIMV) bs[tid] = __ldg(&bvec[tid]);
    __syncthreads();

    const int b = blockIdx.x * 8 + w;
    if (b >= B) return;

    const float bl = bs[lane];
    const float a0 = (lane < KN) ? __ldg(&g_attn0[b * KN + lane]) : 0.f;
    const int   e1 = (lane < KN) ? __ldg(&g_e1id [b * KN + lane]) : 0;
    const int item = __ldg(&items[b]);

    // hop-0 node: item row + 16 e1-row gather
    float x0 = __ldg(&emb[(size_t)item * DIMV + lane]);
    #pragma unroll
    for (int h = 0; h < 2; ++h) {
        float v[8];
        #pragma unroll
        for (int k = 0; k < 8; ++k) {
            int id = __shfl_sync(0xffffffffu, e1, h * 8 + k);
            v[k] = __ldg(&emb[(size_t)id * DIMV + lane]);
        }
        #pragma unroll
        for (int k = 0; k < 8; ++k)
            x0 += __shfl_sync(0xffffffffu, a0, h * 8 + k) * v[k];
    }
    float y0 = bl;
    #pragma unroll
    for (int j = 0; j < DIMV; ++j)
        y0 += __shfl_sync(0xffffffffu, x0, j) * Ws[j * DIMV + lane];
    float xf = sigm(y0);

    // final aggregate over t1 rows (coalesced) + matvec + score
    const float* tb = g_t + (size_t)b * KN * DIMV;
    #pragma unroll
    for (int h = 0; h < 2; ++h) {
        float v[8];
        #pragma unroll
        for (int k = 0; k < 8; ++k)
            v[k] = __ldg(&tb[(h * 8 + k) * DIMV + lane]);
        #pragma unroll
        for (int k = 0; k < 8; ++k)
            xf += __shfl_sync(0xffffffffu, a0, h * 8 + k) * v[k];
    }
    float yf = bl;
    #pragma unroll
    for (int j = 0; j < DIMV; ++j)
        yf += __shfl_sync(0xffffffffu, xf, j) * Ws[j * DIMV + lane];
    float f = tanhf(yf);

    float s = __ldg(&g_uemb[b * DIMV + lane]) * f;
    #pragma unroll
    for (int o = 16; o > 0; o >>= 1) s += __shfl_xor_sync(0xffffffffu, s, o);
    if (lane == 0) out[b] = sigm(s);
}

extern "C" void kernel_launch(void* const* d_in, const int* in_sizes, int n_in,
                              void* d_out, int out_size) {
    const int*   users        = (const int*)  d_in[0];
    const int*   items        = (const int*)  d_in[1];
    const float* entity_emb   = (const float*)d_in[2];
    const float* relation_emb = (const float*)d_in[3];
    const int*   adj_entity   = (const int*)  d_in[4];
    const int*   adj_relation = (const int*)  d_in[5];
    const int*   user_history = (const int*)  d_in[6];
    const float* W            = (const float*)d_in[7];
    const float* b            = (const float*)d_in[8];
    float* out = (float*)d_out;

    int B = in_sizes[0];
    ka_kernel<<<(B + 3) / 4, 256>>>(users, items, entity_emb, relation_emb,
                                    adj_entity, adj_relation, user_history, B);
    kb_kernel<<<(B * 4 + 7) / 8, 256>>>(entity_emb, W, b, B);
    kc_kernel<<<(B + 7) / 8, 256>>>(items, entity_emb, W, b, out, B);
}

// round 16
// speedup vs baseline: 1.0701x; 1.0701x over previous
#include <cuda_runtime.h>
#include <math.h>

#define DIMV 32
#define KN 16
#define NREL 60
#define MAXB 8192

// scratch (device globals)
__device__ float g_uemb [MAXB * DIMV];
__device__ int   g_e1id [MAXB * KN];
__device__ float g_attn0[MAXB * KN];
__device__ int   g_e2id [MAXB * KN * KN];
__device__ float g_attn1[MAXB * KN * KN];
__device__ float g_t    [MAXB * KN * DIMV];

__device__ __forceinline__ float sigm(float x) { return 1.f / (1.f + __expf(-x)); }

__device__ __forceinline__ float softmax16(float sc) {
    float m = sc;
    #pragma unroll
    for (int o = 8; o > 0; o >>= 1) m = fmaxf(m, __shfl_xor_sync(0xffffffffu, m, o, 16));
    float e = __expf(sc - m);
    float s = e;
    #pragma unroll
    for (int o = 8; o > 0; o >>= 1) s += __shfl_xor_sync(0xffffffffu, s, o, 16);
    return e / s;
}

__device__ __forceinline__ float udr_lookup(float u0, float u1, int rid) {
    float a = __shfl_sync(0xffffffffu, u0, rid & 31);
    float b = __shfl_sync(0xffffffffu, u1, rid & 31);
    return (rid < 32) ? a : b;
}

// ---- KA: warp per element; hop-2 loads batched 8-deep. -------------------
__global__ __launch_bounds__(256, 6) void ka_kernel(
    const int*   __restrict__ users,
    const int*   __restrict__ items,
    const float* __restrict__ emb,
    const float* __restrict__ rel,
    const int*   __restrict__ adjE,
    const int*   __restrict__ adjR,
    const int*   __restrict__ hist,
    int B)
{
    __shared__ float rels[NREL * DIMV];   // swizzled [r*32 + ((d+r)&31)]

    const int tid = threadIdx.x, lane = tid & 31, w = tid >> 5;
    #pragma unroll
    for (int i = tid; i < NREL * DIMV; i += 256) {
        int r = i >> 5, d = i & 31;
        rels[r * DIMV + ((d + r) & 31)] = __ldg(&rel[i]);
    }
    __syncthreads();

    const int b = blockIdx.x * 8 + w;
    if (b >= B) return;

    const int uid  = __ldg(&users[b]);
    const int item = __ldg(&items[b]);
    const int kl   = lane & 15;

    const int hid = __ldg(&hist[(size_t)uid  * KN + kl]);
    const int e1  = __ldg(&adjE[(size_t)item * KN + kl]);
    const int r0  = __ldg(&adjR[(size_t)item * KN + kl]);

    // user embedding: batch the 16 independent row loads
    float hv[8];
    float us = 0.f;
    #pragma unroll
    for (int h = 0; h < 2; ++h) {
        #pragma unroll
        for (int k = 0; k < 8; ++k) {
            int id = __shfl_sync(0xffffffffu, hid, h * 8 + k);
            hv[k] = __ldg(&emb[(size_t)id * DIMV + lane]);
        }
        #pragma unroll
        for (int k = 0; k < 8; ++k) us += hv[k];
    }
    const float uemb = us * (1.f / 16.f);
    g_uemb[b * DIMV + lane] = uemb;

    // udotr: lane r holds udotr[r] (u0) and udotr[r+32] (u1)
    float u0 = 0.f, u1 = 0.f;
    const int r2 = lane + 32;
    #pragma unroll
    for (int d = 0; d < DIMV; ++d) {
        float ud = __shfl_sync(0xffffffffu, uemb, d);
        u0 += ud * rels[lane * DIMV + ((d + lane) & 31)];
        if (r2 < NREL) u1 += ud * rels[r2 * DIMV + ((d + r2) & 31)];
    }

    // hop-0 attention + e1 ids
    float a0 = softmax16(udr_lookup(u0, u1, r0));
    if (lane < KN) {
        g_e1id [b * KN + lane] = e1;
        g_attn0[b * KN + lane] = a0;
    }

    // hop-2 adjacency + hop-1 attention: 2 batches of 4 iterations,
    // each batch issues its 8 independent loads before any softmax/store.
    #pragma unroll
    for (int bb = 0; bb < 2; ++bb) {
        int idv[4], ridv[4];
        #pragma unroll
        for (int p = 0; p < 4; ++p) {
            int row  = bb * 8 + 2 * p + (lane >> 4);
            int base = __shfl_sync(0xffffffffu, e1, row);
            idv[p]  = __ldg(&adjE[(size_t)base * KN + kl]);
            ridv[p] = __ldg(&adjR[(size_t)base * KN + kl]);
        }
        #pragma unroll
        for (int p = 0; p < 4; ++p) {
            int row  = bb * 8 + 2 * p + (lane >> 4);
            float a  = softmax16(udr_lookup(u0, u1, ridv[p]));
            size_t o = (size_t)b * 256 + row * KN + kl;
            g_e2id [o] = idv[p];
            g_attn1[o] = a;
        }
    }
}

// ---- KB: warp per quad. Pipelined gather + quad-batched matvec (R14). ----
__global__ __launch_bounds__(256, 5) void kb_kernel(
    const float* __restrict__ emb,
    const float* __restrict__ W,
    const float* __restrict__ bvec,
    int B)
{
    __shared__ float Ws[DIMV * DIMV];
    __shared__ float bs[DIMV];

    const int tid = threadIdx.x, lane = tid & 31, w = tid >> 5;
    #pragma unroll
    for (int i = tid; i < DIMV * DIMV; i += 256) Ws[i] = __ldg(&W[i]);
    if (tid < DIMV) bs[tid] = __ldg(&bvec[tid]);
    __syncthreads();

    const int q = blockIdx.x * 8 + w;
    const int b = q >> 2, quad = q & 3;
    if (b >= B) return;

    const int2*   idp = (const int2*)  (g_e2id  + (size_t)b * 256 + quad * 64);
    const float2* wtp = (const float2*)(g_attn1 + (size_t)b * 256 + quad * 64);
    const int2   id2 = __ldg(&idp[lane]);
    const float2 wt2 = __ldg(&wtp[lane]);

    const int s4 = (lane < 4) ? __ldg(&g_e1id[b * KN + quad * 4 + lane]) : 0;
    float xacc[4];
    #pragma unroll
    for (int t = 0; t < 4; ++t) {
        int sid = __shfl_sync(0xffffffffu, s4, t);
        xacc[t] = __ldg(&emb[(size_t)sid * DIMV + lane]);
    }

    float va[4], vb[4], na[4], nb[4];
    #pragma unroll
    for (int p = 0; p < 4; ++p) {
        int ia = __shfl_sync(0xffffffffu, id2.x, p);
        int ib = __shfl_sync(0xffffffffu, id2.y, p);
        va[p] = __ldg(&emb[(size_t)ia * DIMV + lane]);
        vb[p] = __ldg(&emb[(size_t)ib * DIMV + lane]);
    }

    #pragma unroll
    for (int t = 0; t < 4; ++t) {
        #pragma unroll
        for (int h = 0; h < 2; ++h) {
            const int nt = (h == 1) ? t + 1 : t;
            const int nh = (h == 1) ? 0 : 1;
            if (nt < 4) {
                #pragma unroll
                for (int p = 0; p < 4; ++p) {
                    int src = nt * 8 + nh * 4 + p;
                    int ia = __shfl_sync(0xffffffffu, id2.x, src);
                    int ib = __shfl_sync(0xffffffffu, id2.y, src);
                    na[p] = __ldg(&emb[(size_t)ia * DIMV + lane]);
                    nb[p] = __ldg(&emb[(size_t)ib * DIMV + lane]);
                }
            }
            #pragma unroll
            for (int p = 0; p < 4; ++p) {
                int src = t * 8 + h * 4 + p;
                xacc[t] += __shfl_sync(0xffffffffu, wt2.x, src) * va[p];
                xacc[t] += __shfl_sync(0xffffffffu, wt2.y, src) * vb[p];
            }
            #pragma unroll
            for (int p = 0; p < 4; ++p) { va[p] = na[p]; vb[p] = nb[p]; }
        }
    }

    // quad-batched matvec: each Ws row read once, feeds all 4 tasks
    float y0 = bs[lane], y1 = y0, y2 = y0, y3 = y0;
    #pragma unroll
    for (int j = 0; j < DIMV; ++j) {
        float wj = Ws[j * DIMV + lane];
        y0 += __shfl_sync(0xffffffffu, xacc[0], j) * wj;
        y1 += __shfl_sync(0xffffffffu, xacc[1], j) * wj;
        y2 += __shfl_sync(0xffffffffu, xacc[2], j) * wj;
        y3 += __shfl_sync(0xffffffffu, xacc[3], j) * wj;
    }

    float* tp = g_t + ((size_t)b * KN + quad * 4) * DIMV + lane;
    tp[0 * DIMV] = sigm(y0);
    tp[1 * DIMV] = sigm(y1);
    tp[2 * DIMV] = sigm(y2);
    tp[3 * DIMV] = sigm(y3);
}

// ---- KC: warp per element. hop-0 node + final matvec + score (R14). ------
__global__ __launch_bounds__(256, 4) void kc_kernel(
    const int*   __restrict__ items,
    const float* __restrict__ emb,
    const float* __restrict__ W,
    const float* __restrict__ bvec,
    float*       __restrict__ out,
    int B)
{
    const int tid = threadIdx.x, lane = tid & 31, w = tid >> 5;
    const int b = blockIdx.x * 8 + w;
    if (b >= B) return;

    float Wcol[DIMV];
    #pragma unroll
    for (int j = 0; j < DIMV; ++j) Wcol[j] = __ldg(&W[j * DIMV + lane]);
    const float bl = __ldg(&bvec[lane]);

    const float a0 = (lane < KN) ? __ldg(&g_attn0[b * KN + lane]) : 0.f;
    const int   e1 = (lane < KN) ? __ldg(&g_e1id [b * KN + lane]) : 0;
    const int item = __ldg(&items[b]);

    // hop-0 node: item row + 16 e1-row gather
    float x0 = __ldg(&emb[(size_t)item * DIMV + lane]);
    #pragma unroll
    for (int h = 0; h < 2; ++h) {
        float v[8];
        #pragma unroll
        for (int k = 0; k < 8; ++k) {
            int id = __shfl_sync(0xffffffffu, e1, h * 8 + k);
            v[k] = __ldg(&emb[(size_t)id * DIMV + lane]);
        }
        #pragma unroll
        for (int k = 0; k < 8; ++k)
            x0 += __shfl_sync(0xffffffffu, a0, h * 8 + k) * v[k];
    }
    float y0 = bl;
    #pragma unroll
    for (int j = 0; j < DIMV; ++j)
        y0 += __shfl_sync(0xffffffffu, x0, j) * Wcol[j];
    float xf = sigm(y0);

    // final aggregate over t1 rows (coalesced) + matvec + score
    const float* tb = g_t + (size_t)b * KN * DIMV;
    #pragma unroll
    for (int h = 0; h < 2; ++h) {
        float v[8];
        #pragma unroll
        for (int k = 0; k < 8; ++k)
            v[k] = __ldg(&tb[(h * 8 + k) * DIMV + lane]);
        #pragma unroll
        for (int k = 0; k < 8; ++k)
            xf += __shfl_sync(0xffffffffu, a0, h * 8 + k) * v[k];
    }
    float yf = bl;
    #pragma unroll
    for (int j = 0; j < DIMV; ++j)
        yf += __shfl_sync(0xffffffffu, xf, j) * Wcol[j];
    float f = tanhf(yf);

    float s = __ldg(&g_uemb[b * DIMV + lane]) * f;
    #pragma unroll
    for (int o = 16; o > 0; o >>= 1) s += __shfl_xor_sync(0xffffffffu, s, o);
    if (lane == 0) out[b] = sigm(s);
}

extern "C" void kernel_launch(void* const* d_in, const int* in_sizes, int n_in,
                              void* d_out, int out_size) {
    const int*   users        = (const int*)  d_in[0];
    const int*   items        = (const int*)  d_in[1];
    const float* entity_emb   = (const float*)d_in[2];
    const float* relation_emb = (const float*)d_in[3];
    const int*   adj_entity   = (const int*)  d_in[4];
    const int*   adj_relation = (const int*)  d_in[5];
    const int*   user_history = (const int*)  d_in[6];
    const float* W            = (const float*)d_in[7];
    const float* b            = (const float*)d_in[8];
    float* out = (float*)d_out;

    int B = in_sizes[0];
    ka_kernel<<<(B + 7) / 8, 256>>>(users, items, entity_emb, relation_emb,
                                    adj_entity, adj_relation, user_history, B);
    kb_kernel<<<(B * 4 + 7) / 8, 256>>>(entity_emb, W, b, B);
    kc_kernel<<<(B + 7) / 8, 256>>>(items, entity_emb, W, b, out, B);
}